// round 11
// baseline (speedup 1.0000x reference)
#include <cuda_runtime.h>
#include <math.h>

#define NT   64   // 2 warps per block: warp0 = role A, warp1 = role B
#define EPB  32   // elements per block
#define NJ   7
#define DT_C 0.1f
#define ACT_R 50.0f
#define MAXV 20.0f

struct SC {
    float A[NJ][6];
    float nAw[NJ];
    float G[NJ][36];
    float MR[NJ + 1][9];
    float Mp[NJ + 1][3];
    float MiR[NJ][9];
    float Mip[NJ][3];
    float AeR[9];
    float AeQ[9];
    float g[3];
    float ftip[6];
};

__device__ __forceinline__ void mm33(const float* A, const float* B, float* C) {
#pragma unroll
    for (int r = 0; r < 3; r++)
#pragma unroll
        for (int c = 0; c < 3; c++)
            C[r * 3 + c] = A[r * 3 + 0] * B[0 * 3 + c] + A[r * 3 + 1] * B[1 * 3 + c] + A[r * 3 + 2] * B[2 * 3 + c];
}
__device__ __forceinline__ void mm33_tn(const float* A, const float* B, float* C) {  // A^T * B
#pragma unroll
    for (int r = 0; r < 3; r++)
#pragma unroll
        for (int c = 0; c < 3; c++)
            C[r * 3 + c] = A[0 * 3 + r] * B[0 * 3 + c] + A[1 * 3 + r] * B[1 * 3 + c] + A[2 * 3 + r] * B[2 * 3 + c];
}
// C = S * B, S symmetric 3x3 stored [s00,s01,s02,s11,s12,s22]
__device__ __forceinline__ void mm_symn(const float* S, const float* B, float* C) {
#pragma unroll
    for (int c = 0; c < 3; c++) {
        C[0 * 3 + c] = S[0] * B[0 * 3 + c] + S[1] * B[1 * 3 + c] + S[2] * B[2 * 3 + c];
        C[1 * 3 + c] = S[1] * B[0 * 3 + c] + S[3] * B[1 * 3 + c] + S[4] * B[2 * 3 + c];
        C[2 * 3 + c] = S[2] * B[0 * 3 + c] + S[4] * B[1 * 3 + c] + S[5] * B[2 * 3 + c];
    }
}
__device__ __forceinline__ float dotcc(const float* A, int i, const float* B, int j) {
    return A[0 * 3 + i] * B[0 * 3 + j] + A[1 * 3 + i] * B[1 * 3 + j] + A[2 * 3 + i] * B[2 * 3 + j];
}
__device__ __forceinline__ void mv33(const float* A, const float* x, float* y) {
#pragma unroll
    for (int r = 0; r < 3; r++) y[r] = A[r * 3 + 0] * x[0] + A[r * 3 + 1] * x[1] + A[r * 3 + 2] * x[2];
}
__device__ __forceinline__ void mv33_t(const float* A, const float* x, float* y) {
#pragma unroll
    for (int r = 0; r < 3; r++) y[r] = A[0 * 3 + r] * x[0] + A[1 * 3 + r] * x[1] + A[2 * 3 + r] * x[2];
}
__device__ __forceinline__ void cross3(const float* a, const float* b, float* c) {
    c[0] = a[1] * b[2] - a[2] * b[1];
    c[1] = a[2] * b[0] - a[0] * b[2];
    c[2] = a[0] * b[1] - a[1] * b[0];
}
__device__ __forceinline__ void rodr(float* R, float a, float b, const float* w, float th2) {
    R[0] = 1.f + b * (w[0] * w[0] - th2);
    R[1] = b * w[0] * w[1] - a * w[2];
    R[2] = b * w[0] * w[2] + a * w[1];
    R[3] = b * w[0] * w[1] + a * w[2];
    R[4] = 1.f + b * (w[1] * w[1] - th2);
    R[5] = b * w[1] * w[2] - a * w[0];
    R[6] = b * w[0] * w[2] - a * w[1];
    R[7] = b * w[1] * w[2] + a * w[0];
    R[8] = 1.f + b * (w[2] * w[2] - th2);
}
__device__ __forceinline__ void abc_coeffs(float th, float& a, float& b, float& c) {
    float th2 = th * th;
    if (th < 1e-4f) {
        a = 1.f - th2 * (1.f / 6.f);
        b = 0.5f - th2 * (1.f / 24.f);
        c = (1.f / 6.f) - th2 * (1.f / 120.f);
    } else {
        float sn = __sinf(th), co = __cosf(th);
        float it = __fdividef(1.f, th);
        a = sn * it;
        b = (1.f - co) * (it * it);
        c = (th - sn) * (it * it * it);
    }
}

// adjoint of exp(-A_i q_i) * Minv_i, as (R, Q = skew(p)R)
__device__ __forceinline__ void make_adjoint(const SC* sc, int i, float qi, float* R, float* Q) {
    float Aw[3] = {sc->A[i][0], sc->A[i][1], sc->A[i][2]};
    float Av[3] = {sc->A[i][3], sc->A[i][4], sc->A[i][5]};
    float w[3] = {-Aw[0] * qi, -Aw[1] * qi, -Aw[2] * qi};
    float v[3] = {-Av[0] * qi, -Av[1] * qi, -Av[2] * qi};
    float th = sc->nAw[i] * fabsf(qi);
    float th2 = th * th;
    float a, bb, cc;
    abc_coeffs(th, a, bb, cc);
    float R0[9], Vmx[9];
    rodr(R0, a, bb, w, th2);
    rodr(Vmx, bb, cc, w, th2);
    float p[3];
    mv33(Vmx, v, p);
    mm33(R0, sc->MiR[i], R);
    float pm[3];
    mv33(R0, sc->Mip[i], pm);
    float pT[3] = {pm[0] + p[0], pm[1] + p[1], pm[2] + p[2]};
#pragma unroll
    for (int c = 0; c < 3; c++) {
        Q[0 * 3 + c] = -pT[2] * R[1 * 3 + c] + pT[1] * R[2 * 3 + c];
        Q[1 * 3 + c] = pT[2] * R[0 * 3 + c] - pT[0] * R[2 * 3 + c];
        Q[2 * 3 + c] = -pT[1] * R[0 * 3 + c] + pT[0] * R[1 * 3 + c];
    }
}

#define TRI(r, c) ((r) * ((r) + 1) / 2 + (c))

__global__ void __launch_bounds__(NT) arm_kernel(
    const float* __restrict__ state, const float* __restrict__ torque,
    const float* __restrict__ Mg, const float* __restrict__ Ag,
    const float* __restrict__ Lg, const float* __restrict__ gg,
    const float* __restrict__ fg, float* __restrict__ out, int n) {
    __shared__ SC sc;
    __shared__ float sRt[NJ * 9 * EPB];
    __shared__ float sQt[NJ * 9 * EPB];
    __shared__ float sVs[NJ * 6 * EPB];
    __shared__ float sVd[NJ * 6 * EPB];
    __shared__ float sMm[28 * EPB];
    __shared__ float sRhs[NJ * EPB];

    const int tid = threadIdx.x;
    const int slot = tid & 31;
    const int role = tid >> 5;

#define SRT(i, k) sRt[((i) * 9 + (k)) * EPB + slot]
#define SQT(i, k) sQt[((i) * 9 + (k)) * EPB + slot]
#define SVS(i, k) sVs[((i) * 6 + (k)) * EPB + slot]
#define SVD(i, k) sVd[((i) * 6 + (k)) * EPB + slot]
#define SMM(t)    sMm[(t) * EPB + slot]
#define SRHS(i)   sRhs[(i) * EPB + slot]

    // ---- block-shared constant preprocessing ----
    for (int idx = tid; idx < NJ * 6; idx += NT) ((float*)sc.A)[idx] = Ag[idx];
    for (int i = tid; i < NJ; i += NT) {
        float a0 = Ag[i * 6], a1 = Ag[i * 6 + 1], a2 = Ag[i * 6 + 2];
        sc.nAw[i] = sqrtf(a0 * a0 + a1 * a1 + a2 * a2);
    }
    for (int idx = tid; idx < NJ * 36; idx += NT) {
        int i = idx / 36, rc = idx % 36, r = rc / 6, cc = rc % 6;
        const float* Lr = Lg + i * 36 + r * 6;
        const float* Lc = Lg + i * 36 + cc * 6;
        float s = 0.f;
#pragma unroll
        for (int k = 0; k < 6; k++) s += Lr[k] * Lc[k];
        sc.G[i][rc] = s;
    }
    for (int i = tid; i < NJ + 1; i += NT) {
        const float* m = Mg + i * 16;
#pragma unroll
        for (int r = 0; r < 3; r++) {
#pragma unroll
            for (int c = 0; c < 3; c++) sc.MR[i][r * 3 + c] = m[r * 4 + c];
            sc.Mp[i][r] = m[r * 4 + 3];
        }
        if (i < NJ) {
#pragma unroll
            for (int r = 0; r < 3; r++) {
#pragma unroll
                for (int c = 0; c < 3; c++) sc.MiR[i][r * 3 + c] = m[c * 4 + r];
                sc.Mip[i][r] = -(m[0 * 4 + r] * m[0 * 4 + 3] + m[1 * 4 + r] * m[1 * 4 + 3] + m[2 * 4 + r] * m[2 * 4 + 3]);
            }
        }
    }
    if (tid == 0) {
        const float* m = Mg + NJ * 16;
        float Re[9], pe[3];
#pragma unroll
        for (int r = 0; r < 3; r++) {
#pragma unroll
            for (int c = 0; c < 3; c++) Re[r * 3 + c] = m[c * 4 + r];
            pe[r] = -(m[0 * 4 + r] * m[0 * 4 + 3] + m[1 * 4 + r] * m[1 * 4 + 3] + m[2 * 4 + r] * m[2 * 4 + 3]);
        }
#pragma unroll
        for (int c = 0; c < 3; c++) {
            sc.AeQ[0 * 3 + c] = -pe[2] * Re[1 * 3 + c] + pe[1] * Re[2 * 3 + c];
            sc.AeQ[1 * 3 + c] = pe[2] * Re[0 * 3 + c] - pe[0] * Re[2 * 3 + c];
            sc.AeQ[2 * 3 + c] = -pe[1] * Re[0 * 3 + c] + pe[0] * Re[1 * 3 + c];
        }
#pragma unroll
        for (int k = 0; k < 9; k++) sc.AeR[k] = Re[k];
#pragma unroll
        for (int k = 0; k < 3; k++) sc.g[k] = gg[k];
#pragma unroll
        for (int k = 0; k < 6; k++) sc.ftip[k] = fg[k];
    }
    __syncthreads();

    const int b = blockIdx.x * EPB + slot;
    const bool ok = (b < n);
    const int bl = ok ? b : (n - 1);  // clamped load index; all threads stay for barriers

    float q0[NJ], dq0[NJ], tv[NJ];
#pragma unroll
    for (int i = 0; i < NJ; i++) {
        q0[i] = state[bl * 14 + i];
        dq0[i] = state[bl * 14 + 7 + i];
        tv[i] = torque[bl * 7 + i] * ACT_R;
    }
    float qs[NJ], ds[NJ], aq[NJ], ad[NJ], dd[NJ];
#pragma unroll
    for (int i = 0; i < NJ; i++) { qs[i] = q0[i]; ds[i] = dq0[i]; aq[i] = 0.f; ad[i] = 0.f; }

#pragma unroll 1
    for (int st = 0; st < 4; ++st) {
        // ===== phase 1: adjoints, split across the two warps =====
        if (role == 0) {
#pragma unroll
            for (int i = 0; i < 4; i++) {
                float R[9], Q[9];
                make_adjoint(&sc, i, qs[i], R, Q);
#pragma unroll
                for (int k = 0; k < 9; k++) { SRT(i, k) = R[k]; SQT(i, k) = Q[k]; }
            }
        } else {
#pragma unroll
            for (int i = 4; i < 7; i++) {
                float R[9], Q[9];
                make_adjoint(&sc, i, qs[i], R, Q);
#pragma unroll
                for (int k = 0; k < 9; k++) { SRT(i, k) = R[k]; SQT(i, k) = Q[k]; }
            }
        }
        __syncthreads();

        // ===== phase 2: warp A = forward recursion + bias backward; warp B = CRBA =====
        if (role == 0) {
            // forward twist/accel recursion (ddq = 0, gravity on)
            {
                float Vw[3] = {0.f, 0.f, 0.f}, Vv[3] = {0.f, 0.f, 0.f};
                float Dw[3] = {0.f, 0.f, 0.f}, Dv[3] = {-sc.g[0], -sc.g[1], -sc.g[2]};
#pragma unroll
                for (int i = 0; i < NJ; i++) {
                    float R[9], Q[9];
#pragma unroll
                    for (int k = 0; k < 9; k++) { R[k] = SRT(i, k); Q[k] = SQT(i, k); }
                    float Aw[3] = {sc.A[i][0], sc.A[i][1], sc.A[i][2]};
                    float Av[3] = {sc.A[i][3], sc.A[i][4], sc.A[i][5]};
                    float dqi = ds[i];
                    float t1[3], t2[3], t3[3];
                    mv33(R, Vw, t1);
                    mv33(Q, Vw, t2);
                    mv33(R, Vv, t3);
#pragma unroll
                    for (int k = 0; k < 3; k++) { Vw[k] = t1[k] + Aw[k] * dqi; Vv[k] = t2[k] + t3[k] + Av[k] * dqi; }
                    mv33(R, Dw, t1);
                    mv33(Q, Dw, t2);
                    mv33(R, Dv, t3);
                    float c1[3], c2[3], c3[3];
                    cross3(Vw, Aw, c1);
                    cross3(Vv, Aw, c2);
                    cross3(Vw, Av, c3);
#pragma unroll
                    for (int k = 0; k < 3; k++) {
                        Dw[k] = t1[k] + c1[k] * dqi;
                        Dv[k] = t2[k] + t3[k] + (c2[k] + c3[k]) * dqi;
                    }
#pragma unroll
                    for (int k = 0; k < 3; k++) {
                        SVS(i, k) = Vw[k]; SVS(i, k + 3) = Vv[k];
                        SVD(i, k) = Dw[k]; SVD(i, k + 3) = Dv[k];
                    }
                }
            }
            // backward bias-force recursion -> rhs
            {
                float Fw[3], Fv[3];
                {
                    float fw[3] = {sc.ftip[0], sc.ftip[1], sc.ftip[2]};
                    float fv[3] = {sc.ftip[3], sc.ftip[4], sc.ftip[5]};
                    float t1[3], t2[3], t3[3];
                    mv33_t(sc.AeR, fw, t1);
                    mv33_t(sc.AeQ, fv, t2);
                    mv33_t(sc.AeR, fv, t3);
#pragma unroll
                    for (int k = 0; k < 3; k++) { Fw[k] = t1[k] + t2[k]; Fv[k] = t3[k]; }
                }
#pragma unroll
                for (int ii = 0; ii < NJ; ii++) {
                    const int i = NJ - 1 - ii;
                    float vw[3], vv[3], dw[3], dv[3];
#pragma unroll
                    for (int k = 0; k < 3; k++) {
                        vw[k] = SVS(i, k); vv[k] = SVS(i, k + 3);
                        dw[k] = SVD(i, k); dv[k] = SVD(i, k + 3);
                    }
                    const float* Gi = sc.G[i];
                    float GVw[3], GVv[3], GDw[3], GDv[3];
#pragma unroll
                    for (int r = 0; r < 3; r++) {
                        GVw[r] = Gi[r * 6 + 0] * vw[0] + Gi[r * 6 + 1] * vw[1] + Gi[r * 6 + 2] * vw[2] +
                                 Gi[r * 6 + 3] * vv[0] + Gi[r * 6 + 4] * vv[1] + Gi[r * 6 + 5] * vv[2];
                        GVv[r] = Gi[(r + 3) * 6 + 0] * vw[0] + Gi[(r + 3) * 6 + 1] * vw[1] + Gi[(r + 3) * 6 + 2] * vw[2] +
                                 Gi[(r + 3) * 6 + 3] * vv[0] + Gi[(r + 3) * 6 + 4] * vv[1] + Gi[(r + 3) * 6 + 5] * vv[2];
                        GDw[r] = Gi[r * 6 + 0] * dw[0] + Gi[r * 6 + 1] * dw[1] + Gi[r * 6 + 2] * dw[2] +
                                 Gi[r * 6 + 3] * dv[0] + Gi[r * 6 + 4] * dv[1] + Gi[r * 6 + 5] * dv[2];
                        GDv[r] = Gi[(r + 3) * 6 + 0] * dw[0] + Gi[(r + 3) * 6 + 1] * dw[1] + Gi[(r + 3) * 6 + 2] * dw[2] +
                                 Gi[(r + 3) * 6 + 3] * dv[0] + Gi[(r + 3) * 6 + 4] * dv[1] + Gi[(r + 3) * 6 + 5] * dv[2];
                    }
                    float cw[3], cv[3], cx[3];
                    cross3(vw, GVw, cw);
                    cross3(vv, GVv, cv);
                    cross3(vw, GVv, cx);
#pragma unroll
                    for (int k = 0; k < 3; k++) {
                        Fw[k] += GDw[k] + cw[k] + cv[k];
                        Fv[k] += GDv[k] + cx[k];
                    }
                    SRHS(i) = tv[i] - (Fw[0] * sc.A[i][0] + Fw[1] * sc.A[i][1] + Fw[2] * sc.A[i][2] +
                                       Fv[0] * sc.A[i][3] + Fv[1] * sc.A[i][4] + Fv[2] * sc.A[i][5]);
                    if (i > 0) {
                        float R[9], Q[9];
#pragma unroll
                        for (int k = 0; k < 9; k++) { R[k] = SRT(i, k); Q[k] = SQT(i, k); }
                        float t1[3], t2[3], t3[3];
                        mv33_t(R, Fw, t1);
                        mv33_t(Q, Fv, t2);
                        mv33_t(R, Fv, t3);
#pragma unroll
                        for (int k = 0; k < 3; k++) { Fw[k] = t1[k] + t2[k]; Fv[k] = t3[k]; }
                    }
                }
            }
        } else {
            // ===== warp B: CRBA with symmetric composite inertia =====
            // Gc blocks: ga (sym, upper-left), gb (full, upper-right), gd (sym, lower-right)
            float ga[6], gb[9], gd[6];
            {
                const float* G6 = sc.G[NJ - 1];
                ga[0] = G6[0]; ga[1] = G6[1]; ga[2] = G6[2]; ga[3] = G6[7]; ga[4] = G6[8]; ga[5] = G6[14];
                gb[0] = G6[3]; gb[1] = G6[4]; gb[2] = G6[5];
                gb[3] = G6[9]; gb[4] = G6[10]; gb[5] = G6[11];
                gb[6] = G6[15]; gb[7] = G6[16]; gb[8] = G6[17];
                gd[0] = G6[21]; gd[1] = G6[22]; gd[2] = G6[23]; gd[3] = G6[28]; gd[4] = G6[29]; gd[5] = G6[35];
            }
            float Sw[NJ][3], Sv[NJ][3];
#pragma unroll
            for (int ii = 0; ii < NJ; ii++) {
                const int i = NJ - 1 - ii;
                const float a0 = sc.A[i][0], a1 = sc.A[i][1], a2 = sc.A[i][2];
                const float a3 = sc.A[i][3], a4 = sc.A[i][4], a5 = sc.A[i][5];
                // seed S_i = Gc * A_i
                Sw[i][0] = ga[0] * a0 + ga[1] * a1 + ga[2] * a2 + gb[0] * a3 + gb[1] * a4 + gb[2] * a5;
                Sw[i][1] = ga[1] * a0 + ga[3] * a1 + ga[4] * a2 + gb[3] * a3 + gb[4] * a4 + gb[5] * a5;
                Sw[i][2] = ga[2] * a0 + ga[4] * a1 + ga[5] * a2 + gb[6] * a3 + gb[7] * a4 + gb[8] * a5;
                Sv[i][0] = gb[0] * a0 + gb[3] * a1 + gb[6] * a2 + gd[0] * a3 + gd[1] * a4 + gd[2] * a5;
                Sv[i][1] = gb[1] * a0 + gb[4] * a1 + gb[7] * a2 + gd[1] * a3 + gd[3] * a4 + gd[4] * a5;
                Sv[i][2] = gb[2] * a0 + gb[5] * a1 + gb[8] * a2 + gd[2] * a3 + gd[4] * a4 + gd[5] * a5;
                // mass-matrix column i: Mm[m][i] = S_m . A_i, m >= i
#pragma unroll
                for (int m = 0; m < NJ; m++) {
                    if (m >= i) {
                        SMM(TRI(m, i)) = Sw[m][0] * a0 + Sw[m][1] * a1 + Sw[m][2] * a2 +
                                         Sv[m][0] * a3 + Sv[m][1] * a4 + Sv[m][2] * a5;
                    }
                }
                if (i > 0) {
                    float R[9], Q[9];
#pragma unroll
                    for (int k = 0; k < 9; k++) { R[k] = SRT(i, k); Q[k] = SQT(i, k); }
                    // push live seeds down
#pragma unroll
                    for (int m = 0; m < NJ; m++) {
                        if (m >= i) {
                            float t1[3], t2[3], t3[3];
                            mv33_t(R, Sw[m], t1);
                            mv33_t(Q, Sv[m], t2);
                            mv33_t(R, Sv[m], t3);
#pragma unroll
                            for (int k = 0; k < 3; k++) { Sw[m][k] = t1[k] + t2[k]; Sv[m][k] = t3[k]; }
                        }
                    }
                    // Gc <- AdT^T Gc AdT + G_{i-1}, symmetric form
                    float X[9], Y[9], Z[9], W[9], T[9];
                    mm_symn(gd, R, X);                 // X = Gd R
                    mm33(gb, R, Y);                    // Y = Gb R
                    mm_symn(ga, R, Z);
                    mm33(gb, Q, T);
#pragma unroll
                    for (int k = 0; k < 9; k++) Z[k] += T[k];   // Z = Ga R + Gb Q
                    mm33_tn(gb, R, W);
                    mm_symn(gd, Q, T);
#pragma unroll
                    for (int k = 0; k < 9; k++) W[k] += T[k];   // W = Gb^T R + Gd Q
                    const float* Gp = sc.G[i - 1];
                    float nga[6], ngb[9], ngd[6];
                    nga[0] = dotcc(R, 0, Z, 0) + dotcc(Q, 0, W, 0) + Gp[0];
                    nga[1] = dotcc(R, 0, Z, 1) + dotcc(Q, 0, W, 1) + Gp[1];
                    nga[2] = dotcc(R, 0, Z, 2) + dotcc(Q, 0, W, 2) + Gp[2];
                    nga[3] = dotcc(R, 1, Z, 1) + dotcc(Q, 1, W, 1) + Gp[7];
                    nga[4] = dotcc(R, 1, Z, 2) + dotcc(Q, 1, W, 2) + Gp[8];
                    nga[5] = dotcc(R, 2, Z, 2) + dotcc(Q, 2, W, 2) + Gp[14];
#pragma unroll
                    for (int r = 0; r < 3; r++)
#pragma unroll
                        for (int c = 0; c < 3; c++)
                            ngb[r * 3 + c] = dotcc(R, r, Y, c) + dotcc(Q, r, X, c) + Gp[r * 6 + c + 3];
                    ngd[0] = dotcc(R, 0, X, 0) + Gp[21];
                    ngd[1] = dotcc(R, 0, X, 1) + Gp[22];
                    ngd[2] = dotcc(R, 0, X, 2) + Gp[23];
                    ngd[3] = dotcc(R, 1, X, 1) + Gp[28];
                    ngd[4] = dotcc(R, 1, X, 2) + Gp[29];
                    ngd[5] = dotcc(R, 2, X, 2) + Gp[35];
#pragma unroll
                    for (int k = 0; k < 6; k++) { ga[k] = nga[k]; gd[k] = ngd[k]; }
#pragma unroll
                    for (int k = 0; k < 9; k++) gb[k] = ngb[k];
                }
            }
        }
        __syncthreads();

        // ===== phase 3 (both warps, duplicated): Cholesky solve M dd = rhs =====
        {
            float L[28], rhs[NJ];
#pragma unroll
            for (int t = 0; t < 28; t++) L[t] = SMM(t);
#pragma unroll
            for (int i = 0; i < NJ; i++) rhs[i] = SRHS(i);
#pragma unroll
            for (int k2 = 0; k2 < NJ; k2++) {
                float s = L[TRI(k2, k2)];
#pragma unroll
                for (int m2 = 0; m2 < NJ; m2++)
                    if (m2 < k2) { float l = L[TRI(k2, m2)]; s -= l * l; }
                float inv = rsqrtf(s);
                L[TRI(k2, k2)] = inv;
#pragma unroll
                for (int r = 0; r < NJ; r++) {
                    if (r > k2) {
                        float s2 = L[TRI(r, k2)];
#pragma unroll
                        for (int m2 = 0; m2 < NJ; m2++)
                            if (m2 < k2) s2 -= L[TRI(r, m2)] * L[TRI(k2, m2)];
                        L[TRI(r, k2)] = s2 * inv;
                    }
                }
            }
            float y[NJ];
#pragma unroll
            for (int i = 0; i < NJ; i++) {
                float s = rhs[i];
#pragma unroll
                for (int j = 0; j < NJ; j++)
                    if (j < i) s -= L[TRI(i, j)] * y[j];
                y[i] = s * L[TRI(i, i)];
            }
#pragma unroll
            for (int ii = 0; ii < NJ; ii++) {
                const int i = NJ - 1 - ii;
                float s = y[i];
#pragma unroll
                for (int j = 0; j < NJ; j++)
                    if (j > i) s -= L[TRI(j, i)] * dd[j];
                dd[i] = s * L[TRI(i, i)];
            }
        }

        // ===== RK4 combine (duplicated in both warps) =====
        float w8 = (st == 0 || st == 3) ? 1.f : 2.f;
#pragma unroll
        for (int i = 0; i < NJ; i++) { aq[i] += w8 * ds[i]; ad[i] += w8 * dd[i]; }
        if (st < 3) {
            float hc = (st == 2) ? DT_C : 0.5f * DT_C;
#pragma unroll
            for (int i = 0; i < NJ; i++) {
                qs[i] = q0[i] + hc * ds[i];
                ds[i] = dq0[i] + hc * dd[i];
            }
        }
    }

    const float PI_F = 3.14159265358979323846f;
    const float TWO_PI = 6.28318530717958647692f;
    float qf2[NJ], dqf[NJ];
#pragma unroll
    for (int i = 0; i < NJ; i++) {
        float vq = q0[i] + (DT_C / 6.f) * aq[i];
        float x = vq + PI_F;
        float r = fmodf(x, TWO_PI);
        if (r < 0.f) r += TWO_PI;
        qf2[i] = r - PI_F;
        float vd = dq0[i] + (DT_C / 6.f) * ad[i];
        dqf[i] = fminf(fmaxf(vd, -MAXV), MAXV);
    }

    if (role == 0) {
        // state outputs
        if (ok) {
#pragma unroll
            for (int i = 0; i < NJ; i++) {
                out[b * 14 + i] = qf2[i];
                out[b * 14 + 7 + i] = dqf[i];
            }
        }
    } else {
        // forward kinematics (end-effector x,y)
        float Rk[9] = {1.f, 0.f, 0.f, 0.f, 1.f, 0.f, 0.f, 0.f, 1.f};
        float pk[3] = {0.f, 0.f, 0.f};
#pragma unroll
        for (int i = 0; i < NJ; i++) {
            float Rm2[9];
            mm33(Rk, sc.MR[i], Rm2);
            float pm2[3];
            mv33(Rk, sc.Mp[i], pm2);
#pragma unroll
            for (int k = 0; k < 3; k++) pm2[k] += pk[k];
            float qi = qf2[i];
            float w[3] = {sc.A[i][0] * qi, sc.A[i][1] * qi, sc.A[i][2] * qi};
            float v[3] = {sc.A[i][3] * qi, sc.A[i][4] * qi, sc.A[i][5] * qi};
            float th = sc.nAw[i] * fabsf(qi);
            float th2 = th * th;
            float a, bb, cc;
            abc_coeffs(th, a, bb, cc);
            float Re[9], Vmx[9];
            rodr(Re, a, bb, w, th2);
            rodr(Vmx, bb, cc, w, th2);
            float pe[3];
            mv33(Vmx, v, pe);
            float Rn[9];
            mm33(Rm2, Re, Rn);
            float pn[3];
            mv33(Rm2, pe, pn);
#pragma unroll
            for (int k = 0; k < 3; k++) pk[k] = pn[k] + pm2[k];
#pragma unroll
            for (int k = 0; k < 9; k++) Rk[k] = Rn[k];
        }
        float pf[3];
        mv33(Rk, sc.Mp[NJ], pf);
        if (ok) {
            out[(size_t)n * 14 + b * 2 + 0] = pf[0] + pk[0];
            out[(size_t)n * 14 + b * 2 + 1] = pf[1] + pk[1];
        }
    }
}

extern "C" void kernel_launch(void* const* d_in, const int* in_sizes, int n_in,
                              void* d_out, int out_size) {
    const float* state = (const float*)d_in[0];
    const float* torque = (const float*)d_in[1];
    const float* M = (const float*)d_in[2];
    const float* A = (const float*)d_in[3];
    const float* L = (const float*)d_in[4];
    const float* g = (const float*)d_in[5];
    const float* f = (const float*)d_in[6];
    int n = in_sizes[0] / 14;
    int grid = (n + EPB - 1) / EPB;
    arm_kernel<<<grid, NT>>>(state, torque, M, A, L, g, f, (float*)d_out, n);
}

// round 12
// speedup vs baseline: 1.4020x; 1.4020x over previous
#include <cuda_runtime.h>
#include <math.h>

#define NT   32
#define NJ   7
#define DT_C 0.1f
#define ACT_R 50.0f
#define MAXV 20.0f

struct SC {
    float A[NJ][6];
    float nAw[NJ];
    float G[NJ][36];
    float MR[NJ + 1][9];
    float Mp[NJ + 1][3];
    float MiR[NJ][9];
    float Mip[NJ][3];
    float AeR[9];
    float AeQ[9];
    float g[3];
    float ftip[6];
};

__device__ __forceinline__ void mm33(const float* A, const float* B, float* C) {
#pragma unroll
    for (int r = 0; r < 3; r++)
#pragma unroll
        for (int c = 0; c < 3; c++)
            C[r * 3 + c] = A[r * 3 + 0] * B[0 * 3 + c] + A[r * 3 + 1] * B[1 * 3 + c] + A[r * 3 + 2] * B[2 * 3 + c];
}
__device__ __forceinline__ void mm33_tn(const float* A, const float* B, float* C) {  // A^T * B
#pragma unroll
    for (int r = 0; r < 3; r++)
#pragma unroll
        for (int c = 0; c < 3; c++)
            C[r * 3 + c] = A[0 * 3 + r] * B[0 * 3 + c] + A[1 * 3 + r] * B[1 * 3 + c] + A[2 * 3 + r] * B[2 * 3 + c];
}
// C = S * B, S symmetric 3x3 stored [s00,s01,s02,s11,s12,s22]
__device__ __forceinline__ void mm_symn(const float* S, const float* B, float* C) {
#pragma unroll
    for (int c = 0; c < 3; c++) {
        C[0 * 3 + c] = S[0] * B[0 * 3 + c] + S[1] * B[1 * 3 + c] + S[2] * B[2 * 3 + c];
        C[1 * 3 + c] = S[1] * B[0 * 3 + c] + S[3] * B[1 * 3 + c] + S[4] * B[2 * 3 + c];
        C[2 * 3 + c] = S[2] * B[0 * 3 + c] + S[4] * B[1 * 3 + c] + S[5] * B[2 * 3 + c];
    }
}
__device__ __forceinline__ float dotcc(const float* A, int i, const float* B, int j) {
    return A[0 * 3 + i] * B[0 * 3 + j] + A[1 * 3 + i] * B[1 * 3 + j] + A[2 * 3 + i] * B[2 * 3 + j];
}
__device__ __forceinline__ void mv33(const float* A, const float* x, float* y) {
#pragma unroll
    for (int r = 0; r < 3; r++) y[r] = A[r * 3 + 0] * x[0] + A[r * 3 + 1] * x[1] + A[r * 3 + 2] * x[2];
}
__device__ __forceinline__ void mv33_t(const float* A, const float* x, float* y) {
#pragma unroll
    for (int r = 0; r < 3; r++) y[r] = A[0 * 3 + r] * x[0] + A[1 * 3 + r] * x[1] + A[2 * 3 + r] * x[2];
}
__device__ __forceinline__ void cross3(const float* a, const float* b, float* c) {
    c[0] = a[1] * b[2] - a[2] * b[1];
    c[1] = a[2] * b[0] - a[0] * b[2];
    c[2] = a[0] * b[1] - a[1] * b[0];
}
__device__ __forceinline__ void rodr(float* R, float a, float b, const float* w, float th2) {
    R[0] = 1.f + b * (w[0] * w[0] - th2);
    R[1] = b * w[0] * w[1] - a * w[2];
    R[2] = b * w[0] * w[2] + a * w[1];
    R[3] = b * w[0] * w[1] + a * w[2];
    R[4] = 1.f + b * (w[1] * w[1] - th2);
    R[5] = b * w[1] * w[2] - a * w[0];
    R[6] = b * w[0] * w[2] - a * w[1];
    R[7] = b * w[1] * w[2] + a * w[0];
    R[8] = 1.f + b * (w[2] * w[2] - th2);
}
__device__ __forceinline__ void abc_coeffs(float th, float& a, float& b, float& c) {
    float th2 = th * th;
    if (th < 1e-4f) {
        a = 1.f - th2 * (1.f / 6.f);
        b = 0.5f - th2 * (1.f / 24.f);
        c = (1.f / 6.f) - th2 * (1.f / 120.f);
    } else {
        float sn = __sinf(th), co = __cosf(th);
        float it = __fdividef(1.f, th);
        a = sn * it;
        b = (1.f - co) * (it * it);
        c = (th - sn) * (it * it * it);
    }
}

#define TRI(r, c) ((r) * ((r) + 1) / 2 + (c))

__global__ void __launch_bounds__(NT) arm_kernel(
    const float* __restrict__ state, const float* __restrict__ torque,
    const float* __restrict__ Mg, const float* __restrict__ Ag,
    const float* __restrict__ Lg, const float* __restrict__ gg,
    const float* __restrict__ fg, float* __restrict__ out, int n) {
    __shared__ SC sc;
    __shared__ float sRt[NJ * 9 * NT];
    __shared__ float sQt[NJ * 9 * NT];
    __shared__ float sVs[NJ * 6 * NT];
    __shared__ float sVd[NJ * 6 * NT];

    const int tid = threadIdx.x;

#define SRT(i, k) sRt[((i) * 9 + (k)) * NT + tid]
#define SQT(i, k) sQt[((i) * 9 + (k)) * NT + tid]
#define SVS(i, k) sVs[((i) * 6 + (k)) * NT + tid]
#define SVD(i, k) sVd[((i) * 6 + (k)) * NT + tid]

    // ---- block-shared constant preprocessing ----
    for (int idx = tid; idx < NJ * 6; idx += NT) ((float*)sc.A)[idx] = Ag[idx];
    for (int i = tid; i < NJ; i += NT) {
        float a0 = Ag[i * 6], a1 = Ag[i * 6 + 1], a2 = Ag[i * 6 + 2];
        sc.nAw[i] = sqrtf(a0 * a0 + a1 * a1 + a2 * a2);
    }
    for (int idx = tid; idx < NJ * 36; idx += NT) {
        int i = idx / 36, rc = idx % 36, r = rc / 6, cc = rc % 6;
        const float* Lr = Lg + i * 36 + r * 6;
        const float* Lc = Lg + i * 36 + cc * 6;
        float s = 0.f;
#pragma unroll
        for (int k = 0; k < 6; k++) s += Lr[k] * Lc[k];
        sc.G[i][rc] = s;
    }
    for (int i = tid; i < NJ + 1; i += NT) {
        const float* m = Mg + i * 16;
#pragma unroll
        for (int r = 0; r < 3; r++) {
#pragma unroll
            for (int c = 0; c < 3; c++) sc.MR[i][r * 3 + c] = m[r * 4 + c];
            sc.Mp[i][r] = m[r * 4 + 3];
        }
        if (i < NJ) {
#pragma unroll
            for (int r = 0; r < 3; r++) {
#pragma unroll
                for (int c = 0; c < 3; c++) sc.MiR[i][r * 3 + c] = m[c * 4 + r];
                sc.Mip[i][r] = -(m[0 * 4 + r] * m[0 * 4 + 3] + m[1 * 4 + r] * m[1 * 4 + 3] + m[2 * 4 + r] * m[2 * 4 + 3]);
            }
        }
    }
    if (tid == 0) {
        const float* m = Mg + NJ * 16;
        float Re[9], pe[3];
#pragma unroll
        for (int r = 0; r < 3; r++) {
#pragma unroll
            for (int c = 0; c < 3; c++) Re[r * 3 + c] = m[c * 4 + r];
            pe[r] = -(m[0 * 4 + r] * m[0 * 4 + 3] + m[1 * 4 + r] * m[1 * 4 + 3] + m[2 * 4 + r] * m[2 * 4 + 3]);
        }
#pragma unroll
        for (int c = 0; c < 3; c++) {
            sc.AeQ[0 * 3 + c] = -pe[2] * Re[1 * 3 + c] + pe[1] * Re[2 * 3 + c];
            sc.AeQ[1 * 3 + c] = pe[2] * Re[0 * 3 + c] - pe[0] * Re[2 * 3 + c];
            sc.AeQ[2 * 3 + c] = -pe[1] * Re[0 * 3 + c] + pe[0] * Re[1 * 3 + c];
        }
#pragma unroll
        for (int k = 0; k < 9; k++) sc.AeR[k] = Re[k];
#pragma unroll
        for (int k = 0; k < 3; k++) sc.g[k] = gg[k];
#pragma unroll
        for (int k = 0; k < 6; k++) sc.ftip[k] = fg[k];
    }
    __syncthreads();

    const int b = blockIdx.x * NT + tid;
    if (b >= n) return;

    float q0[NJ], dq0[NJ], tv[NJ];
#pragma unroll
    for (int i = 0; i < NJ; i++) {
        q0[i] = state[b * 14 + i];
        dq0[i] = state[b * 14 + 7 + i];
        tv[i] = torque[b * 7 + i] * ACT_R;
    }
    float qs[NJ], ds[NJ], aq[NJ], ad[NJ], dd[NJ];
#pragma unroll
    for (int i = 0; i < NJ; i++) { qs[i] = q0[i]; ds[i] = dq0[i]; aq[i] = 0.f; ad[i] = 0.f; }

#pragma unroll 1
    for (int st = 0; st < 4; ++st) {
        // ===== forward pass: fused adjoint computation + twist/accel recursion =====
        {
            float Vw[3] = {0.f, 0.f, 0.f}, Vv[3] = {0.f, 0.f, 0.f};
            float Dw[3] = {0.f, 0.f, 0.f}, Dv[3] = {-sc.g[0], -sc.g[1], -sc.g[2]};
#pragma unroll
            for (int i = 0; i < NJ; i++) {
                float qi = qs[i];
                float Aw[3] = {sc.A[i][0], sc.A[i][1], sc.A[i][2]};
                float Av[3] = {sc.A[i][3], sc.A[i][4], sc.A[i][5]};
                float w[3] = {-Aw[0] * qi, -Aw[1] * qi, -Aw[2] * qi};
                float v[3] = {-Av[0] * qi, -Av[1] * qi, -Av[2] * qi};
                float th = sc.nAw[i] * fabsf(qi);
                float th2 = th * th;
                float a, bb, cc;
                abc_coeffs(th, a, bb, cc);
                float R0[9], Vmx[9];
                rodr(R0, a, bb, w, th2);
                rodr(Vmx, bb, cc, w, th2);
                float p[3];
                mv33(Vmx, v, p);
                float R[9];
                mm33(R0, sc.MiR[i], R);
                float pm[3];
                mv33(R0, sc.Mip[i], pm);
                float pT[3] = {pm[0] + p[0], pm[1] + p[1], pm[2] + p[2]};
                float Q[9];
#pragma unroll
                for (int c = 0; c < 3; c++) {
                    Q[0 * 3 + c] = -pT[2] * R[1 * 3 + c] + pT[1] * R[2 * 3 + c];
                    Q[1 * 3 + c] = pT[2] * R[0 * 3 + c] - pT[0] * R[2 * 3 + c];
                    Q[2 * 3 + c] = -pT[1] * R[0 * 3 + c] + pT[0] * R[1 * 3 + c];
                }
#pragma unroll
                for (int k = 0; k < 9; k++) { SRT(i, k) = R[k]; SQT(i, k) = Q[k]; }

                float dqi = ds[i];
                float t1[3], t2[3], t3[3];
                mv33(R, Vw, t1);
                mv33(Q, Vw, t2);
                mv33(R, Vv, t3);
#pragma unroll
                for (int k = 0; k < 3; k++) { Vw[k] = t1[k] + Aw[k] * dqi; Vv[k] = t2[k] + t3[k] + Av[k] * dqi; }
                mv33(R, Dw, t1);
                mv33(Q, Dw, t2);
                mv33(R, Dv, t3);
                float c1[3], c2[3], c3[3];
                cross3(Vw, Aw, c1);
                cross3(Vv, Aw, c2);
                cross3(Vw, Av, c3);
#pragma unroll
                for (int k = 0; k < 3; k++) {
                    Dw[k] = t1[k] + c1[k] * dqi;
                    Dv[k] = t2[k] + t3[k] + (c2[k] + c3[k]) * dqi;
                }
#pragma unroll
                for (int k = 0; k < 3; k++) {
                    SVS(i, k) = Vw[k]; SVS(i, k + 3) = Vv[k];
                    SVD(i, k) = Dw[k]; SVD(i, k + 3) = Dv[k];
                }
            }
        }

        // ===== backward pass: bias forces + CRBA (symmetric Gc, triangular Mm), merged =====
        float rhs[NJ];
        float Mm[28];
        {
            float Sw[NJ][3], Sv[NJ][3];
            float ga[6], gb[9], gd[6];
            {
                const float* G6 = sc.G[NJ - 1];
                ga[0] = G6[0]; ga[1] = G6[1]; ga[2] = G6[2]; ga[3] = G6[7]; ga[4] = G6[8]; ga[5] = G6[14];
                gb[0] = G6[3]; gb[1] = G6[4]; gb[2] = G6[5];
                gb[3] = G6[9]; gb[4] = G6[10]; gb[5] = G6[11];
                gb[6] = G6[15]; gb[7] = G6[16]; gb[8] = G6[17];
                gd[0] = G6[21]; gd[1] = G6[22]; gd[2] = G6[23]; gd[3] = G6[28]; gd[4] = G6[29]; gd[5] = G6[35];
            }

            float Fw[3], Fv[3];
            {
                float fw[3] = {sc.ftip[0], sc.ftip[1], sc.ftip[2]};
                float fv[3] = {sc.ftip[3], sc.ftip[4], sc.ftip[5]};
                float t1[3], t2[3], t3[3];
                mv33_t(sc.AeR, fw, t1);
                mv33_t(sc.AeQ, fv, t2);
                mv33_t(sc.AeR, fv, t3);
#pragma unroll
                for (int k = 0; k < 3; k++) { Fw[k] = t1[k] + t2[k]; Fv[k] = t3[k]; }
            }

#pragma unroll
            for (int ii = 0; ii < NJ; ii++) {
                const int i = NJ - 1 - ii;
                const float a0 = sc.A[i][0], a1 = sc.A[i][1], a2 = sc.A[i][2];
                const float a3 = sc.A[i][3], a4 = sc.A[i][4], a5 = sc.A[i][5];

                // seed S_i = Gc * A_i (symmetric blocks)
                Sw[i][0] = ga[0] * a0 + ga[1] * a1 + ga[2] * a2 + gb[0] * a3 + gb[1] * a4 + gb[2] * a5;
                Sw[i][1] = ga[1] * a0 + ga[3] * a1 + ga[4] * a2 + gb[3] * a3 + gb[4] * a4 + gb[5] * a5;
                Sw[i][2] = ga[2] * a0 + ga[4] * a1 + ga[5] * a2 + gb[6] * a3 + gb[7] * a4 + gb[8] * a5;
                Sv[i][0] = gb[0] * a0 + gb[3] * a1 + gb[6] * a2 + gd[0] * a3 + gd[1] * a4 + gd[2] * a5;
                Sv[i][1] = gb[1] * a0 + gb[4] * a1 + gb[7] * a2 + gd[1] * a3 + gd[3] * a4 + gd[4] * a5;
                Sv[i][2] = gb[2] * a0 + gb[5] * a1 + gb[8] * a2 + gd[2] * a3 + gd[4] * a4 + gd[5] * a5;

                // mass-matrix column i: Mm[TRI(m,i)] = S_m . A_i, m >= i
#pragma unroll
                for (int m = 0; m < NJ; m++) {
                    if (m >= i) {
                        Mm[TRI(m, i)] = Sw[m][0] * a0 + Sw[m][1] * a1 + Sw[m][2] * a2 +
                                        Sv[m][0] * a3 + Sv[m][1] * a4 + Sv[m][2] * a5;
                    }
                }

                // bias-force accumulation at joint i
                {
                    float vw[3], vv[3], dw[3], dv[3];
#pragma unroll
                    for (int k = 0; k < 3; k++) {
                        vw[k] = SVS(i, k); vv[k] = SVS(i, k + 3);
                        dw[k] = SVD(i, k); dv[k] = SVD(i, k + 3);
                    }
                    const float* Gi = sc.G[i];
                    float GVw[3], GVv[3], GDw[3], GDv[3];
#pragma unroll
                    for (int r = 0; r < 3; r++) {
                        GVw[r] = Gi[r * 6 + 0] * vw[0] + Gi[r * 6 + 1] * vw[1] + Gi[r * 6 + 2] * vw[2] +
                                 Gi[r * 6 + 3] * vv[0] + Gi[r * 6 + 4] * vv[1] + Gi[r * 6 + 5] * vv[2];
                        GVv[r] = Gi[(r + 3) * 6 + 0] * vw[0] + Gi[(r + 3) * 6 + 1] * vw[1] + Gi[(r + 3) * 6 + 2] * vw[2] +
                                 Gi[(r + 3) * 6 + 3] * vv[0] + Gi[(r + 3) * 6 + 4] * vv[1] + Gi[(r + 3) * 6 + 5] * vv[2];
                        GDw[r] = Gi[r * 6 + 0] * dw[0] + Gi[r * 6 + 1] * dw[1] + Gi[r * 6 + 2] * dw[2] +
                                 Gi[r * 6 + 3] * dv[0] + Gi[r * 6 + 4] * dv[1] + Gi[r * 6 + 5] * dv[2];
                        GDv[r] = Gi[(r + 3) * 6 + 0] * dw[0] + Gi[(r + 3) * 6 + 1] * dw[1] + Gi[(r + 3) * 6 + 2] * dw[2] +
                                 Gi[(r + 3) * 6 + 3] * dv[0] + Gi[(r + 3) * 6 + 4] * dv[1] + Gi[(r + 3) * 6 + 5] * dv[2];
                    }
                    float cw[3], cv[3], cx[3];
                    cross3(vw, GVw, cw);
                    cross3(vv, GVv, cv);
                    cross3(vw, GVv, cx);
#pragma unroll
                    for (int k = 0; k < 3; k++) {
                        Fw[k] += GDw[k] + cw[k] + cv[k];
                        Fv[k] += GDv[k] + cx[k];
                    }
                    rhs[i] = tv[i] - (Fw[0] * a0 + Fw[1] * a1 + Fw[2] * a2 +
                                      Fv[0] * a3 + Fv[1] * a4 + Fv[2] * a5);
                }

                if (i > 0) {
                    float R[9], Q[9];
#pragma unroll
                    for (int k = 0; k < 9; k++) { R[k] = SRT(i, k); Q[k] = SQT(i, k); }
                    // push bias force down
                    {
                        float t1[3], t2[3], t3[3];
                        mv33_t(R, Fw, t1);
                        mv33_t(Q, Fv, t2);
                        mv33_t(R, Fv, t3);
#pragma unroll
                        for (int k = 0; k < 3; k++) { Fw[k] = t1[k] + t2[k]; Fv[k] = t3[k]; }
                    }
                    // push live seeds down (independent chains)
#pragma unroll
                    for (int m = 0; m < NJ; m++) {
                        if (m >= i) {
                            float t1[3], t2[3], t3[3];
                            mv33_t(R, Sw[m], t1);
                            mv33_t(Q, Sv[m], t2);
                            mv33_t(R, Sv[m], t3);
#pragma unroll
                            for (int k = 0; k < 3; k++) { Sw[m][k] = t1[k] + t2[k]; Sv[m][k] = t3[k]; }
                        }
                    }
                    // Gc <- AdT^T Gc AdT + G_{i-1}, symmetric form
                    float X[9], Y[9], Z[9], W[9], T[9];
                    mm_symn(gd, R, X);                 // X = Gd R
                    mm33(gb, R, Y);                    // Y = Gb R
                    mm_symn(ga, R, Z);
                    mm33(gb, Q, T);
#pragma unroll
                    for (int k = 0; k < 9; k++) Z[k] += T[k];   // Z = Ga R + Gb Q
                    mm33_tn(gb, R, W);
                    mm_symn(gd, Q, T);
#pragma unroll
                    for (int k = 0; k < 9; k++) W[k] += T[k];   // W = Gb^T R + Gd Q
                    const float* Gp = sc.G[i - 1];
                    float nga[6], ngb[9], ngd[6];
                    nga[0] = dotcc(R, 0, Z, 0) + dotcc(Q, 0, W, 0) + Gp[0];
                    nga[1] = dotcc(R, 0, Z, 1) + dotcc(Q, 0, W, 1) + Gp[1];
                    nga[2] = dotcc(R, 0, Z, 2) + dotcc(Q, 0, W, 2) + Gp[2];
                    nga[3] = dotcc(R, 1, Z, 1) + dotcc(Q, 1, W, 1) + Gp[7];
                    nga[4] = dotcc(R, 1, Z, 2) + dotcc(Q, 1, W, 2) + Gp[8];
                    nga[5] = dotcc(R, 2, Z, 2) + dotcc(Q, 2, W, 2) + Gp[14];
#pragma unroll
                    for (int r = 0; r < 3; r++)
#pragma unroll
                        for (int c = 0; c < 3; c++)
                            ngb[r * 3 + c] = dotcc(R, r, Y, c) + dotcc(Q, r, X, c) + Gp[r * 6 + c + 3];
                    ngd[0] = dotcc(R, 0, X, 0) + Gp[21];
                    ngd[1] = dotcc(R, 0, X, 1) + Gp[22];
                    ngd[2] = dotcc(R, 0, X, 2) + Gp[23];
                    ngd[3] = dotcc(R, 1, X, 1) + Gp[28];
                    ngd[4] = dotcc(R, 1, X, 2) + Gp[29];
                    ngd[5] = dotcc(R, 2, X, 2) + Gp[35];
#pragma unroll
                    for (int k = 0; k < 6; k++) { ga[k] = nga[k]; gd[k] = ngd[k]; }
#pragma unroll
                    for (int k = 0; k < 9; k++) gb[k] = ngb[k];
                }
            }
        }

        // ===== Cholesky solve: M dd = rhs (triangular storage, fully unrolled) =====
        {
#pragma unroll
            for (int k2 = 0; k2 < NJ; k2++) {
                float s = Mm[TRI(k2, k2)];
#pragma unroll
                for (int m2 = 0; m2 < NJ; m2++)
                    if (m2 < k2) { float l = Mm[TRI(k2, m2)]; s -= l * l; }
                float inv = rsqrtf(s);
                Mm[TRI(k2, k2)] = inv;
#pragma unroll
                for (int r = 0; r < NJ; r++) {
                    if (r > k2) {
                        float s2 = Mm[TRI(r, k2)];
#pragma unroll
                        for (int m2 = 0; m2 < NJ; m2++)
                            if (m2 < k2) s2 -= Mm[TRI(r, m2)] * Mm[TRI(k2, m2)];
                        Mm[TRI(r, k2)] = s2 * inv;
                    }
                }
            }
            float y[NJ];
#pragma unroll
            for (int i = 0; i < NJ; i++) {
                float s = rhs[i];
#pragma unroll
                for (int j = 0; j < NJ; j++)
                    if (j < i) s -= Mm[TRI(i, j)] * y[j];
                y[i] = s * Mm[TRI(i, i)];
            }
#pragma unroll
            for (int ii = 0; ii < NJ; ii++) {
                const int i = NJ - 1 - ii;
                float s = y[i];
#pragma unroll
                for (int j = 0; j < NJ; j++)
                    if (j > i) s -= Mm[TRI(j, i)] * dd[j];
                dd[i] = s * Mm[TRI(i, i)];
            }
        }

        // ===== RK4 combine =====
        float w8 = (st == 0 || st == 3) ? 1.f : 2.f;
#pragma unroll
        for (int i = 0; i < NJ; i++) { aq[i] += w8 * ds[i]; ad[i] += w8 * dd[i]; }
        if (st < 3) {
            float hc = (st == 2) ? DT_C : 0.5f * DT_C;
#pragma unroll
            for (int i = 0; i < NJ; i++) {
                qs[i] = q0[i] + hc * ds[i];
                ds[i] = dq0[i] + hc * dd[i];
            }
        }
    }

    const float PI_F = 3.14159265358979323846f;
    const float TWO_PI = 6.28318530717958647692f;
    float qf2[NJ], dqf[NJ];
#pragma unroll
    for (int i = 0; i < NJ; i++) {
        float vq = q0[i] + (DT_C / 6.f) * aq[i];
        float x = vq + PI_F;
        float r = fmodf(x, TWO_PI);
        if (r < 0.f) r += TWO_PI;
        qf2[i] = r - PI_F;
        float vd = dq0[i] + (DT_C / 6.f) * ad[i];
        dqf[i] = fminf(fmaxf(vd, -MAXV), MAXV);
    }

    // ===== forward kinematics (end-effector x,y) =====
    float Rk[9] = {1.f, 0.f, 0.f, 0.f, 1.f, 0.f, 0.f, 0.f, 1.f};
    float pk[3] = {0.f, 0.f, 0.f};
#pragma unroll
    for (int i = 0; i < NJ; i++) {
        float Rm2[9];
        mm33(Rk, sc.MR[i], Rm2);
        float pm2[3];
        mv33(Rk, sc.Mp[i], pm2);
#pragma unroll
        for (int k = 0; k < 3; k++) pm2[k] += pk[k];
        float qi = qf2[i];
        float w[3] = {sc.A[i][0] * qi, sc.A[i][1] * qi, sc.A[i][2] * qi};
        float v[3] = {sc.A[i][3] * qi, sc.A[i][4] * qi, sc.A[i][5] * qi};
        float th = sc.nAw[i] * fabsf(qi);
        float th2 = th * th;
        float a, bb, cc;
        abc_coeffs(th, a, bb, cc);
        float Re[9], Vmx[9];
        rodr(Re, a, bb, w, th2);
        rodr(Vmx, bb, cc, w, th2);
        float pe[3];
        mv33(Vmx, v, pe);
        float Rn[9];
        mm33(Rm2, Re, Rn);
        float pn[3];
        mv33(Rm2, pe, pn);
#pragma unroll
        for (int k = 0; k < 3; k++) pk[k] = pn[k] + pm2[k];
#pragma unroll
        for (int k = 0; k < 9; k++) Rk[k] = Rn[k];
    }
    float pf[3];
    mv33(Rk, sc.Mp[NJ], pf);
    float eex = pf[0] + pk[0];
    float eey = pf[1] + pk[1];

    // ===== outputs: [n,14] state then [n,2] ee, concatenated flat =====
#pragma unroll
    for (int i = 0; i < NJ; i++) {
        out[b * 14 + i] = qf2[i];
        out[b * 14 + 7 + i] = dqf[i];
    }
    out[(size_t)n * 14 + b * 2 + 0] = eex;
    out[(size_t)n * 14 + b * 2 + 1] = eey;
}

extern "C" void kernel_launch(void* const* d_in, const int* in_sizes, int n_in,
                              void* d_out, int out_size) {
    const float* state = (const float*)d_in[0];
    const float* torque = (const float*)d_in[1];
    const float* M = (const float*)d_in[2];
    const float* A = (const float*)d_in[3];
    const float* L = (const float*)d_in[4];
    const float* g = (const float*)d_in[5];
    const float* f = (const float*)d_in[6];
    int n = in_sizes[0] / 14;
    int grid = (n + NT - 1) / NT;
    arm_kernel<<<grid, NT>>>(state, torque, M, A, L, g, f, (float*)d_out, n);
}

// round 14
// speedup vs baseline: 1.6103x; 1.1485x over previous
#include <cuda_runtime.h>
#include <math.h>

#define NT   32
#define NJ   7
#define DT_C 0.1f
#define ACT_R 50.0f
#define MAXV 20.0f

struct SC {
    float A[NJ][6];
    float nAw[NJ];
    float G[NJ][36];
    float MR[NJ + 1][9];
    float Mp[NJ + 1][3];
    float MiR[NJ][9];
    float Mip[NJ][3];
    float ft6[6];   // AdT_end^T * Ftip (constant tip wrench in frame 6)
    float g[3];
};

__device__ __forceinline__ void mm33(const float* A, const float* B, float* C) {
#pragma unroll
    for (int r = 0; r < 3; r++)
#pragma unroll
        for (int c = 0; c < 3; c++)
            C[r * 3 + c] = A[r * 3 + 0] * B[0 * 3 + c] + A[r * 3 + 1] * B[1 * 3 + c] + A[r * 3 + 2] * B[2 * 3 + c];
}
__device__ __forceinline__ void mv33(const float* A, const float* x, float* y) {
#pragma unroll
    for (int r = 0; r < 3; r++) y[r] = A[r * 3 + 0] * x[0] + A[r * 3 + 1] * x[1] + A[r * 3 + 2] * x[2];
}
__device__ __forceinline__ void mv33_t(const float* A, const float* x, float* y) {
#pragma unroll
    for (int r = 0; r < 3; r++) y[r] = A[0 * 3 + r] * x[0] + A[1 * 3 + r] * x[1] + A[2 * 3 + r] * x[2];
}
__device__ __forceinline__ void cross3(const float* a, const float* b, float* c) {
    c[0] = a[1] * b[2] - a[2] * b[1];
    c[1] = a[2] * b[0] - a[0] * b[2];
    c[2] = a[0] * b[1] - a[1] * b[0];
}
__device__ __forceinline__ void rodr(float* R, float a, float b, const float* w, float th2) {
    R[0] = 1.f + b * (w[0] * w[0] - th2);
    R[1] = b * w[0] * w[1] - a * w[2];
    R[2] = b * w[0] * w[2] + a * w[1];
    R[3] = b * w[0] * w[1] + a * w[2];
    R[4] = 1.f + b * (w[1] * w[1] - th2);
    R[5] = b * w[1] * w[2] - a * w[0];
    R[6] = b * w[0] * w[2] - a * w[1];
    R[7] = b * w[1] * w[2] + a * w[0];
    R[8] = 1.f + b * (w[2] * w[2] - th2);
}
__device__ __forceinline__ void abc_coeffs(float th, float& a, float& b, float& c) {
    float th2 = th * th;
    if (th < 1e-4f) {
        a = 1.f - th2 * (1.f / 6.f);
        b = 0.5f - th2 * (1.f / 24.f);
        c = (1.f / 6.f) - th2 * (1.f / 120.f);
    } else {
        float sn = __sinf(th), co = __cosf(th);
        float it = __fdividef(1.f, th);
        a = sn * it;
        b = (1.f - co) * (it * it);
        c = (th - sn) * (it * it * it);
    }
}

// adjoint of exp(-A_i q_i) * Minv_i, as (R, Q = skew(p)R)
__device__ __forceinline__ void make_adjoint(const SC* sc, int i, float qi, float* R, float* Q) {
    float w[3] = {-sc->A[i][0] * qi, -sc->A[i][1] * qi, -sc->A[i][2] * qi};
    float v[3] = {-sc->A[i][3] * qi, -sc->A[i][4] * qi, -sc->A[i][5] * qi};
    float th = sc->nAw[i] * fabsf(qi);
    float th2 = th * th;
    float a, bb, cc;
    abc_coeffs(th, a, bb, cc);
    float R0[9], Vmx[9];
    rodr(R0, a, bb, w, th2);
    rodr(Vmx, bb, cc, w, th2);
    float p[3];
    mv33(Vmx, v, p);
    mm33(R0, sc->MiR[i], R);
    float pm[3];
    mv33(R0, sc->Mip[i], pm);
    float pT[3] = {pm[0] + p[0], pm[1] + p[1], pm[2] + p[2]};
#pragma unroll
    for (int c = 0; c < 3; c++) {
        Q[0 * 3 + c] = -pT[2] * R[1 * 3 + c] + pT[1] * R[2 * 3 + c];
        Q[1 * 3 + c] = pT[2] * R[0 * 3 + c] - pT[0] * R[2 * 3 + c];
        Q[2 * 3 + c] = -pT[1] * R[0 * 3 + c] + pT[0] * R[1 * 3 + c];
    }
}

#define TRI(r, c) ((r) * ((r) + 1) / 2 + (c))

__global__ void __launch_bounds__(NT) arm_kernel(
    const float* __restrict__ state, const float* __restrict__ torque,
    const float* __restrict__ Mg, const float* __restrict__ Ag,
    const float* __restrict__ Lg, const float* __restrict__ gg,
    const float* __restrict__ fg, float* __restrict__ out, int n) {
    __shared__ SC sc;
    const int tid = threadIdx.x;

    // ---- block-shared constant preprocessing ----
    for (int idx = tid; idx < NJ * 6; idx += NT) ((float*)sc.A)[idx] = Ag[idx];
    for (int i = tid; i < NJ; i += NT) {
        float a0 = Ag[i * 6], a1 = Ag[i * 6 + 1], a2 = Ag[i * 6 + 2];
        sc.nAw[i] = sqrtf(a0 * a0 + a1 * a1 + a2 * a2);
    }
    for (int idx = tid; idx < NJ * 36; idx += NT) {
        int i = idx / 36, rc = idx % 36, r = rc / 6, cc = rc % 6;
        const float* Lr = Lg + i * 36 + r * 6;
        const float* Lc = Lg + i * 36 + cc * 6;
        float s = 0.f;
#pragma unroll
        for (int k = 0; k < 6; k++) s += Lr[k] * Lc[k];
        sc.G[i][rc] = s;
    }
    for (int i = tid; i < NJ + 1; i += NT) {
        const float* m = Mg + i * 16;
#pragma unroll
        for (int r = 0; r < 3; r++) {
#pragma unroll
            for (int c = 0; c < 3; c++) sc.MR[i][r * 3 + c] = m[r * 4 + c];
            sc.Mp[i][r] = m[r * 4 + 3];
        }
        if (i < NJ) {
#pragma unroll
            for (int r = 0; r < 3; r++) {
#pragma unroll
                for (int c = 0; c < 3; c++) sc.MiR[i][r * 3 + c] = m[c * 4 + r];
                sc.Mip[i][r] = -(m[0 * 4 + r] * m[0 * 4 + 3] + m[1 * 4 + r] * m[1 * 4 + 3] + m[2 * 4 + r] * m[2 * 4 + 3]);
            }
        }
    }
    if (tid == 0) {
        const float* m = Mg + NJ * 16;
        float Re[9], pe[3], AeQ[9];
#pragma unroll
        for (int r = 0; r < 3; r++) {
#pragma unroll
            for (int c = 0; c < 3; c++) Re[r * 3 + c] = m[c * 4 + r];
            pe[r] = -(m[0 * 4 + r] * m[0 * 4 + 3] + m[1 * 4 + r] * m[1 * 4 + 3] + m[2 * 4 + r] * m[2 * 4 + 3]);
        }
#pragma unroll
        for (int c = 0; c < 3; c++) {
            AeQ[0 * 3 + c] = -pe[2] * Re[1 * 3 + c] + pe[1] * Re[2 * 3 + c];
            AeQ[1 * 3 + c] = pe[2] * Re[0 * 3 + c] - pe[0] * Re[2 * 3 + c];
            AeQ[2 * 3 + c] = -pe[1] * Re[0 * 3 + c] + pe[0] * Re[1 * 3 + c];
        }
        float fw[3] = {fg[0], fg[1], fg[2]};
        float fv[3] = {fg[3], fg[4], fg[5]};
        float t1[3], t2[3], t3[3];
        mv33_t(Re, fw, t1);
        mv33_t(AeQ, fv, t2);
        mv33_t(Re, fv, t3);
#pragma unroll
        for (int k = 0; k < 3; k++) { sc.ft6[k] = t1[k] + t2[k]; sc.ft6[k + 3] = t3[k]; }
#pragma unroll
        for (int k = 0; k < 3; k++) sc.g[k] = gg[k];
    }
    __syncthreads();

    const int b = blockIdx.x * NT + tid;
    if (b >= n) return;

    float q0[NJ], dq0[NJ], tv[NJ];
#pragma unroll
    for (int i = 0; i < NJ; i++) {
        q0[i] = state[b * 14 + i];
        dq0[i] = state[b * 14 + 7 + i];
        tv[i] = torque[b * 7 + i] * ACT_R;
    }
    float qs[NJ], ds[NJ], aq[NJ], ad[NJ], dd[NJ];
#pragma unroll
    for (int i = 0; i < NJ; i++) { qs[i] = q0[i]; ds[i] = dq0[i]; aq[i] = 0.f; ad[i] = 0.f; }

#pragma unroll 1
    for (int st = 0; st < 4; ++st) {
        // ===== single forward sweep: adjoints + twists/accels + bias torques + mass matrix =====
        float Pw[NJ][3], Pv[NJ][3];   // joint axes pushed into current frame
        float Mm[28];                 // mass matrix, lower triangle (accumulated)
        float hh[NJ];                 // bias torques (accumulated)
#pragma unroll
        for (int t = 0; t < 28; t++) Mm[t] = 0.f;
#pragma unroll
        for (int i = 0; i < NJ; i++) hh[i] = 0.f;

        float Vw[3] = {0.f, 0.f, 0.f}, Vv[3] = {0.f, 0.f, 0.f};
        float Dw[3] = {0.f, 0.f, 0.f}, Dv[3] = {-sc.g[0], -sc.g[1], -sc.g[2]};

#pragma unroll
        for (int i = 0; i < NJ; i++) {
            float R[9], Q[9];
            make_adjoint(&sc, i, qs[i], R, Q);

            // push previously-seen axes into frame i: P <- [R Pw ; Q Pw + R Pv]
#pragma unroll
            for (int j = 0; j < NJ; j++) {
                if (j < i) {
                    float t1[3], t2[3], t3[3];
                    mv33(R, Pw[j], t1);
                    mv33(Q, Pw[j], t2);
                    mv33(R, Pv[j], t3);
#pragma unroll
                    for (int k = 0; k < 3; k++) { Pw[j][k] = t1[k]; Pv[j][k] = t2[k] + t3[k]; }
                }
            }
            Pw[i][0] = sc.A[i][0]; Pw[i][1] = sc.A[i][1]; Pw[i][2] = sc.A[i][2];
            Pv[i][0] = sc.A[i][3]; Pv[i][1] = sc.A[i][4]; Pv[i][2] = sc.A[i][5];

            // twist / accel update
            float dqi = ds[i];
            {
                float t1[3], t2[3], t3[3];
                mv33(R, Vw, t1);
                mv33(Q, Vw, t2);
                mv33(R, Vv, t3);
#pragma unroll
                for (int k = 0; k < 3; k++) { Vw[k] = t1[k] + Pw[i][k] * dqi; Vv[k] = t2[k] + t3[k] + Pv[i][k] * dqi; }
                mv33(R, Dw, t1);
                mv33(Q, Dw, t2);
                mv33(R, Dv, t3);
                float c1[3], c2[3], c3[3];
                cross3(Vw, Pw[i], c1);
                cross3(Vv, Pw[i], c2);
                cross3(Vw, Pv[i], c3);
#pragma unroll
                for (int k = 0; k < 3; k++) {
                    Dw[k] = t1[k] + c1[k] * dqi;
                    Dv[k] = t2[k] + t3[k] + (c2[k] + c3[k]) * dqi;
                }
            }

            const float* Gi = sc.G[i];
            // link-local wrench f_i = G V̇ + [Vw×(GV)w + Vv×(GV)v ; Vw×(GV)v]
            float GVw[3], GVv[3], fw[3], fv[3];
#pragma unroll
            for (int r = 0; r < 3; r++) {
                GVw[r] = Gi[r * 6 + 0] * Vw[0] + Gi[r * 6 + 1] * Vw[1] + Gi[r * 6 + 2] * Vw[2] +
                         Gi[r * 6 + 3] * Vv[0] + Gi[r * 6 + 4] * Vv[1] + Gi[r * 6 + 5] * Vv[2];
                GVv[r] = Gi[(r + 3) * 6 + 0] * Vw[0] + Gi[(r + 3) * 6 + 1] * Vw[1] + Gi[(r + 3) * 6 + 2] * Vw[2] +
                         Gi[(r + 3) * 6 + 3] * Vv[0] + Gi[(r + 3) * 6 + 4] * Vv[1] + Gi[(r + 3) * 6 + 5] * Vv[2];
                fw[r] = Gi[r * 6 + 0] * Dw[0] + Gi[r * 6 + 1] * Dw[1] + Gi[r * 6 + 2] * Dw[2] +
                        Gi[r * 6 + 3] * Dv[0] + Gi[r * 6 + 4] * Dv[1] + Gi[r * 6 + 5] * Dv[2];
                fv[r] = Gi[(r + 3) * 6 + 0] * Dw[0] + Gi[(r + 3) * 6 + 1] * Dw[1] + Gi[(r + 3) * 6 + 2] * Dw[2] +
                        Gi[(r + 3) * 6 + 3] * Dv[0] + Gi[(r + 3) * 6 + 4] * Dv[1] + Gi[(r + 3) * 6 + 5] * Dv[2];
            }
            {
                float cw[3], cv[3], cx[3];
                cross3(Vw, GVw, cw);
                cross3(Vv, GVv, cv);
                cross3(Vw, GVv, cx);
#pragma unroll
                for (int k = 0; k < 3; k++) { fw[k] += cw[k] + cv[k]; fv[k] += cx[k]; }
            }

            // bias accumulation: hh[a] += P_a · f_i  (a <= i)
#pragma unroll
            for (int a = 0; a < NJ; a++) {
                if (a <= i) {
                    hh[a] += Pw[a][0] * fw[0] + Pw[a][1] * fw[1] + Pw[a][2] * fw[2] +
                             Pv[a][0] * fv[0] + Pv[a][1] * fv[1] + Pv[a][2] * fv[2];
                }
            }
            // tip wrench enters at the last link's frame
            if (i == NJ - 1) {
#pragma unroll
                for (int a = 0; a < NJ; a++) {
                    hh[a] += Pw[a][0] * sc.ft6[0] + Pw[a][1] * sc.ft6[1] + Pw[a][2] * sc.ft6[2] +
                             Pv[a][0] * sc.ft6[3] + Pv[a][1] * sc.ft6[4] + Pv[a][2] * sc.ft6[5];
                }
            }

            // mass-matrix accumulation: Mm[a,b] += P_a · (G_i P_b), b <= a <= i
#pragma unroll
            for (int bb2 = 0; bb2 < NJ; bb2++) {
                if (bb2 <= i) {
                    float Tw[3], Tv[3];
#pragma unroll
                    for (int r = 0; r < 3; r++) {
                        Tw[r] = Gi[r * 6 + 0] * Pw[bb2][0] + Gi[r * 6 + 1] * Pw[bb2][1] + Gi[r * 6 + 2] * Pw[bb2][2] +
                                Gi[r * 6 + 3] * Pv[bb2][0] + Gi[r * 6 + 4] * Pv[bb2][1] + Gi[r * 6 + 5] * Pv[bb2][2];
                        Tv[r] = Gi[(r + 3) * 6 + 0] * Pw[bb2][0] + Gi[(r + 3) * 6 + 1] * Pw[bb2][1] + Gi[(r + 3) * 6 + 2] * Pw[bb2][2] +
                                Gi[(r + 3) * 6 + 3] * Pv[bb2][0] + Gi[(r + 3) * 6 + 4] * Pv[bb2][1] + Gi[(r + 3) * 6 + 5] * Pv[bb2][2];
                    }
#pragma unroll
                    for (int a = 0; a < NJ; a++) {
                        if (a >= bb2 && a <= i) {
                            Mm[TRI(a, bb2)] += Pw[a][0] * Tw[0] + Pw[a][1] * Tw[1] + Pw[a][2] * Tw[2] +
                                               Pv[a][0] * Tv[0] + Pv[a][1] * Tv[1] + Pv[a][2] * Tv[2];
                        }
                    }
                }
            }
        }

        // ===== Cholesky solve: M dd = tau - h =====
        {
            float rhs[NJ];
#pragma unroll
            for (int i = 0; i < NJ; i++) rhs[i] = tv[i] - hh[i];
#pragma unroll
            for (int k2 = 0; k2 < NJ; k2++) {
                float s = Mm[TRI(k2, k2)];
#pragma unroll
                for (int m2 = 0; m2 < NJ; m2++)
                    if (m2 < k2) { float l = Mm[TRI(k2, m2)]; s -= l * l; }
                float inv = rsqrtf(s);
                Mm[TRI(k2, k2)] = inv;
#pragma unroll
                for (int r = 0; r < NJ; r++) {
                    if (r > k2) {
                        float s2 = Mm[TRI(r, k2)];
#pragma unroll
                        for (int m2 = 0; m2 < NJ; m2++)
                            if (m2 < k2) s2 -= Mm[TRI(r, m2)] * Mm[TRI(k2, m2)];
                        Mm[TRI(r, k2)] = s2 * inv;
                    }
                }
            }
            float y[NJ];
#pragma unroll
            for (int i = 0; i < NJ; i++) {
                float s = rhs[i];
#pragma unroll
                for (int j = 0; j < NJ; j++)
                    if (j < i) s -= Mm[TRI(i, j)] * y[j];
                y[i] = s * Mm[TRI(i, i)];
            }
#pragma unroll
            for (int ii = 0; ii < NJ; ii++) {
                const int i = NJ - 1 - ii;
                float s = y[i];
#pragma unroll
                for (int j = 0; j < NJ; j++)
                    if (j > i) s -= Mm[TRI(j, i)] * dd[j];
                dd[i] = s * Mm[TRI(i, i)];
            }
        }

        // ===== RK4 combine =====
        float w8 = (st == 0 || st == 3) ? 1.f : 2.f;
#pragma unroll
        for (int i = 0; i < NJ; i++) { aq[i] += w8 * ds[i]; ad[i] += w8 * dd[i]; }
        if (st < 3) {
            float hc = (st == 2) ? DT_C : 0.5f * DT_C;
#pragma unroll
            for (int i = 0; i < NJ; i++) {
                qs[i] = q0[i] + hc * ds[i];
                ds[i] = dq0[i] + hc * dd[i];
            }
        }
    }

    const float PI_F = 3.14159265358979323846f;
    const float TWO_PI = 6.28318530717958647692f;
    float qf2[NJ], dqf[NJ];
#pragma unroll
    for (int i = 0; i < NJ; i++) {
        float vq = q0[i] + (DT_C / 6.f) * aq[i];
        float x = vq + PI_F;
        float r = fmodf(x, TWO_PI);
        if (r < 0.f) r += TWO_PI;
        qf2[i] = r - PI_F;
        float vd = dq0[i] + (DT_C / 6.f) * ad[i];
        dqf[i] = fminf(fmaxf(vd, -MAXV), MAXV);
    }

    // ===== forward kinematics (end-effector x,y) =====
    float Rk[9] = {1.f, 0.f, 0.f, 0.f, 1.f, 0.f, 0.f, 0.f, 1.f};
    float pk[3] = {0.f, 0.f, 0.f};
#pragma unroll
    for (int i = 0; i < NJ; i++) {
        float Rm2[9];
        mm33(Rk, sc.MR[i], Rm2);
        float pm2[3];
        mv33(Rk, sc.Mp[i], pm2);
#pragma unroll
        for (int k = 0; k < 3; k++) pm2[k] += pk[k];
        float qi = qf2[i];
        float w[3] = {sc.A[i][0] * qi, sc.A[i][1] * qi, sc.A[i][2] * qi};
        float v[3] = {sc.A[i][3] * qi, sc.A[i][4] * qi, sc.A[i][5] * qi};
        float th = sc.nAw[i] * fabsf(qi);
        float th2 = th * th;
        float a, bb, cc;
        abc_coeffs(th, a, bb, cc);
        float Re[9], Vmx[9];
        rodr(Re, a, bb, w, th2);
        rodr(Vmx, bb, cc, w, th2);
        float pe[3];
        mv33(Vmx, v, pe);
        float Rn[9];
        mm33(Rm2, Re, Rn);
        float pn[3];
        mv33(Rm2, pe, pn);
#pragma unroll
        for (int k = 0; k < 3; k++) pk[k] = pn[k] + pm2[k];
#pragma unroll
        for (int k = 0; k < 9; k++) Rk[k] = Rn[k];
    }
    float pf[3];
    mv33(Rk, sc.Mp[NJ], pf);
    float eex = pf[0] + pk[0];
    float eey = pf[1] + pk[1];

    // ===== outputs: [n,14] state then [n,2] ee, concatenated flat =====
#pragma unroll
    for (int i = 0; i < NJ; i++) {
        out[b * 14 + i] = qf2[i];
        out[b * 14 + 7 + i] = dqf[i];
    }
    out[(size_t)n * 14 + b * 2 + 0] = eex;
    out[(size_t)n * 14 + b * 2 + 1] = eey;
}

extern "C" void kernel_launch(void* const* d_in, const int* in_sizes, int n_in,
                              void* d_out, int out_size) {
    const float* state = (const float*)d_in[0];
    const float* torque = (const float*)d_in[1];
    const float* M = (const float*)d_in[2];
    const float* A = (const float*)d_in[3];
    const float* L = (const float*)d_in[4];
    const float* g = (const float*)d_in[5];
    const float* f = (const float*)d_in[6];
    int n = in_sizes[0] / 14;
    int grid = (n + NT - 1) / NT;
    arm_kernel<<<grid, NT>>>(state, torque, M, A, L, g, f, (float*)d_out, n);
}

// round 15
// speedup vs baseline: 1.6911x; 1.0502x over previous
#include <cuda_runtime.h>
#include <math.h>

#define NT   32
#define NJ   7
#define DT_C 0.1f
#define ACT_R 50.0f
#define MAXV 20.0f

struct SC {
    float A[NJ][6];
    float nAw[NJ];
    float G[NJ][36];
    float MR[NJ + 1][9];
    float Mp[NJ + 1][3];
    float MiR[NJ][9];
    float Mip[NJ][3];
    float ft6[6];   // AdT_end^T * Ftip (constant tip wrench in frame 6)
    float g[3];
};

__device__ __forceinline__ void mm33(const float* A, const float* B, float* C) {
#pragma unroll
    for (int r = 0; r < 3; r++)
#pragma unroll
        for (int c = 0; c < 3; c++)
            C[r * 3 + c] = A[r * 3 + 0] * B[0 * 3 + c] + A[r * 3 + 1] * B[1 * 3 + c] + A[r * 3 + 2] * B[2 * 3 + c];
}
__device__ __forceinline__ void mv33(const float* A, const float* x, float* y) {
#pragma unroll
    for (int r = 0; r < 3; r++) y[r] = A[r * 3 + 0] * x[0] + A[r * 3 + 1] * x[1] + A[r * 3 + 2] * x[2];
}
__device__ __forceinline__ void mv33_t(const float* A, const float* x, float* y) {
#pragma unroll
    for (int r = 0; r < 3; r++) y[r] = A[0 * 3 + r] * x[0] + A[1 * 3 + r] * x[1] + A[2 * 3 + r] * x[2];
}
__device__ __forceinline__ void cross3(const float* a, const float* b, float* c) {
    c[0] = a[1] * b[2] - a[2] * b[1];
    c[1] = a[2] * b[0] - a[0] * b[2];
    c[2] = a[0] * b[1] - a[1] * b[0];
}
__device__ __forceinline__ void rodr(float* R, float a, float b, const float* w, float th2) {
    R[0] = 1.f + b * (w[0] * w[0] - th2);
    R[1] = b * w[0] * w[1] - a * w[2];
    R[2] = b * w[0] * w[2] + a * w[1];
    R[3] = b * w[0] * w[1] + a * w[2];
    R[4] = 1.f + b * (w[1] * w[1] - th2);
    R[5] = b * w[1] * w[2] - a * w[0];
    R[6] = b * w[0] * w[2] - a * w[1];
    R[7] = b * w[1] * w[2] + a * w[0];
    R[8] = 1.f + b * (w[2] * w[2] - th2);
}
__device__ __forceinline__ void abc_coeffs(float th, float& a, float& b, float& c) {
    float th2 = th * th;
    if (th < 1e-4f) {
        a = 1.f - th2 * (1.f / 6.f);
        b = 0.5f - th2 * (1.f / 24.f);
        c = (1.f / 6.f) - th2 * (1.f / 120.f);
    } else {
        float sn = __sinf(th), co = __cosf(th);
        float it = __fdividef(1.f, th);
        a = sn * it;
        b = (1.f - co) * (it * it);
        c = (th - sn) * (it * it * it);
    }
}

// adjoint of exp(-A_i q_i) * Minv_i, as (R, Q = skew(p)R)
__device__ __forceinline__ void make_adjoint(const SC* sc, int i, float qi, float* R, float* Q) {
    float w[3] = {-sc->A[i][0] * qi, -sc->A[i][1] * qi, -sc->A[i][2] * qi};
    float v[3] = {-sc->A[i][3] * qi, -sc->A[i][4] * qi, -sc->A[i][5] * qi};
    float th = sc->nAw[i] * fabsf(qi);
    float th2 = th * th;
    float a, bb, cc;
    abc_coeffs(th, a, bb, cc);
    float R0[9], Vmx[9];
    rodr(R0, a, bb, w, th2);
    rodr(Vmx, bb, cc, w, th2);
    float p[3];
    mv33(Vmx, v, p);
    mm33(R0, sc->MiR[i], R);
    float pm[3];
    mv33(R0, sc->Mip[i], pm);
    float pT[3] = {pm[0] + p[0], pm[1] + p[1], pm[2] + p[2]};
#pragma unroll
    for (int c = 0; c < 3; c++) {
        Q[0 * 3 + c] = -pT[2] * R[1 * 3 + c] + pT[1] * R[2 * 3 + c];
        Q[1 * 3 + c] = pT[2] * R[0 * 3 + c] - pT[0] * R[2 * 3 + c];
        Q[2 * 3 + c] = -pT[1] * R[0 * 3 + c] + pT[0] * R[1 * 3 + c];
    }
}

#define TRI(r, c) ((r) * ((r) + 1) / 2 + (c))

__global__ void __launch_bounds__(NT) arm_kernel(
    const float* __restrict__ state, const float* __restrict__ torque,
    const float* __restrict__ Mg, const float* __restrict__ Ag,
    const float* __restrict__ Lg, const float* __restrict__ gg,
    const float* __restrict__ fg, float* __restrict__ out, int n) {
    __shared__ SC sc;
    // cold per-element state: q0, dq0, tv, aq, ad (35 floats) — slot-strided, conflict-free
    __shared__ float sQ0[NJ * NT];
    __shared__ float sDq0[NJ * NT];
    __shared__ float sTv[NJ * NT];
    __shared__ float sAq[NJ * NT];
    __shared__ float sAd[NJ * NT];

    const int tid = threadIdx.x;

#define SQ0(i)  sQ0[(i) * NT + tid]
#define SDQ0(i) sDq0[(i) * NT + tid]
#define STV(i)  sTv[(i) * NT + tid]
#define SAQ(i)  sAq[(i) * NT + tid]
#define SAD(i)  sAd[(i) * NT + tid]

    // ---- block-shared constant preprocessing ----
    for (int idx = tid; idx < NJ * 6; idx += NT) ((float*)sc.A)[idx] = Ag[idx];
    for (int i = tid; i < NJ; i += NT) {
        float a0 = Ag[i * 6], a1 = Ag[i * 6 + 1], a2 = Ag[i * 6 + 2];
        sc.nAw[i] = sqrtf(a0 * a0 + a1 * a1 + a2 * a2);
    }
    for (int idx = tid; idx < NJ * 36; idx += NT) {
        int i = idx / 36, rc = idx % 36, r = rc / 6, cc = rc % 6;
        const float* Lr = Lg + i * 36 + r * 6;
        const float* Lc = Lg + i * 36 + cc * 6;
        float s = 0.f;
#pragma unroll
        for (int k = 0; k < 6; k++) s += Lr[k] * Lc[k];
        sc.G[i][rc] = s;
    }
    for (int i = tid; i < NJ + 1; i += NT) {
        const float* m = Mg + i * 16;
#pragma unroll
        for (int r = 0; r < 3; r++) {
#pragma unroll
            for (int c = 0; c < 3; c++) sc.MR[i][r * 3 + c] = m[r * 4 + c];
            sc.Mp[i][r] = m[r * 4 + 3];
        }
        if (i < NJ) {
#pragma unroll
            for (int r = 0; r < 3; r++) {
#pragma unroll
                for (int c = 0; c < 3; c++) sc.MiR[i][r * 3 + c] = m[c * 4 + r];
                sc.Mip[i][r] = -(m[0 * 4 + r] * m[0 * 4 + 3] + m[1 * 4 + r] * m[1 * 4 + 3] + m[2 * 4 + r] * m[2 * 4 + 3]);
            }
        }
    }
    if (tid == 0) {
        const float* m = Mg + NJ * 16;
        float Re[9], pe[3], AeQ[9];
#pragma unroll
        for (int r = 0; r < 3; r++) {
#pragma unroll
            for (int c = 0; c < 3; c++) Re[r * 3 + c] = m[c * 4 + r];
            pe[r] = -(m[0 * 4 + r] * m[0 * 4 + 3] + m[1 * 4 + r] * m[1 * 4 + 3] + m[2 * 4 + r] * m[2 * 4 + 3]);
        }
#pragma unroll
        for (int c = 0; c < 3; c++) {
            AeQ[0 * 3 + c] = -pe[2] * Re[1 * 3 + c] + pe[1] * Re[2 * 3 + c];
            AeQ[1 * 3 + c] = pe[2] * Re[0 * 3 + c] - pe[0] * Re[2 * 3 + c];
            AeQ[2 * 3 + c] = -pe[1] * Re[0 * 3 + c] + pe[0] * Re[1 * 3 + c];
        }
        float fw[3] = {fg[0], fg[1], fg[2]};
        float fv[3] = {fg[3], fg[4], fg[5]};
        float t1[3], t2[3], t3[3];
        mv33_t(Re, fw, t1);
        mv33_t(AeQ, fv, t2);
        mv33_t(Re, fv, t3);
#pragma unroll
        for (int k = 0; k < 3; k++) { sc.ft6[k] = t1[k] + t2[k]; sc.ft6[k + 3] = t3[k]; }
#pragma unroll
        for (int k = 0; k < 3; k++) sc.g[k] = gg[k];
    }
    __syncthreads();

    const int b = blockIdx.x * NT + tid;
    if (b >= n) return;

    float qs[NJ], ds[NJ], dd[NJ];
#pragma unroll
    for (int i = 0; i < NJ; i++) {
        float q = state[b * 14 + i];
        float dq = state[b * 14 + 7 + i];
        SQ0(i) = q;
        SDQ0(i) = dq;
        STV(i) = torque[b * 7 + i] * ACT_R;
        SAQ(i) = 0.f;
        SAD(i) = 0.f;
        qs[i] = q;
        ds[i] = dq;
    }

#pragma unroll 1
    for (int st = 0; st < 4; ++st) {
        // ===== single forward sweep: adjoints + twists/accels + bias torques + mass matrix =====
        float Pw[NJ][3], Pv[NJ][3];   // joint axes pushed into current frame
        float Mm[28];                 // mass matrix, lower triangle (accumulated)
        float hh[NJ];                 // bias torques (accumulated)
#pragma unroll
        for (int t = 0; t < 28; t++) Mm[t] = 0.f;
#pragma unroll
        for (int i = 0; i < NJ; i++) hh[i] = 0.f;

        float Vw[3] = {0.f, 0.f, 0.f}, Vv[3] = {0.f, 0.f, 0.f};
        float Dw[3] = {0.f, 0.f, 0.f}, Dv[3] = {-sc.g[0], -sc.g[1], -sc.g[2]};

#pragma unroll
        for (int i = 0; i < NJ; i++) {
            float R[9], Q[9];
            make_adjoint(&sc, i, qs[i], R, Q);

            // push previously-seen axes into frame i: P <- [R Pw ; Q Pw + R Pv]
#pragma unroll
            for (int j = 0; j < NJ; j++) {
                if (j < i) {
                    float t1[3], t2[3], t3[3];
                    mv33(R, Pw[j], t1);
                    mv33(Q, Pw[j], t2);
                    mv33(R, Pv[j], t3);
#pragma unroll
                    for (int k = 0; k < 3; k++) { Pw[j][k] = t1[k]; Pv[j][k] = t2[k] + t3[k]; }
                }
            }
            Pw[i][0] = sc.A[i][0]; Pw[i][1] = sc.A[i][1]; Pw[i][2] = sc.A[i][2];
            Pv[i][0] = sc.A[i][3]; Pv[i][1] = sc.A[i][4]; Pv[i][2] = sc.A[i][5];

            // twist / accel update
            float dqi = ds[i];
            {
                float t1[3], t2[3], t3[3];
                mv33(R, Vw, t1);
                mv33(Q, Vw, t2);
                mv33(R, Vv, t3);
#pragma unroll
                for (int k = 0; k < 3; k++) { Vw[k] = t1[k] + Pw[i][k] * dqi; Vv[k] = t2[k] + t3[k] + Pv[i][k] * dqi; }
                mv33(R, Dw, t1);
                mv33(Q, Dw, t2);
                mv33(R, Dv, t3);
                float c1[3], c2[3], c3[3];
                cross3(Vw, Pw[i], c1);
                cross3(Vv, Pw[i], c2);
                cross3(Vw, Pv[i], c3);
#pragma unroll
                for (int k = 0; k < 3; k++) {
                    Dw[k] = t1[k] + c1[k] * dqi;
                    Dv[k] = t2[k] + t3[k] + (c2[k] + c3[k]) * dqi;
                }
            }

            const float* Gi = sc.G[i];
            // link-local wrench f_i = G V̇ + [Vw×(GV)w + Vv×(GV)v ; Vw×(GV)v]
            float GVw[3], GVv[3], fw[3], fv[3];
#pragma unroll
            for (int r = 0; r < 3; r++) {
                GVw[r] = Gi[r * 6 + 0] * Vw[0] + Gi[r * 6 + 1] * Vw[1] + Gi[r * 6 + 2] * Vw[2] +
                         Gi[r * 6 + 3] * Vv[0] + Gi[r * 6 + 4] * Vv[1] + Gi[r * 6 + 5] * Vv[2];
                GVv[r] = Gi[(r + 3) * 6 + 0] * Vw[0] + Gi[(r + 3) * 6 + 1] * Vw[1] + Gi[(r + 3) * 6 + 2] * Vw[2] +
                         Gi[(r + 3) * 6 + 3] * Vv[0] + Gi[(r + 3) * 6 + 4] * Vv[1] + Gi[(r + 3) * 6 + 5] * Vv[2];
                fw[r] = Gi[r * 6 + 0] * Dw[0] + Gi[r * 6 + 1] * Dw[1] + Gi[r * 6 + 2] * Dw[2] +
                        Gi[r * 6 + 3] * Dv[0] + Gi[r * 6 + 4] * Dv[1] + Gi[r * 6 + 5] * Dv[2];
                fv[r] = Gi[(r + 3) * 6 + 0] * Dw[0] + Gi[(r + 3) * 6 + 1] * Dw[1] + Gi[(r + 3) * 6 + 2] * Dw[2] +
                        Gi[(r + 3) * 6 + 3] * Dv[0] + Gi[(r + 3) * 6 + 4] * Dv[1] + Gi[(r + 3) * 6 + 5] * Dv[2];
            }
            {
                float cw[3], cv[3], cx[3];
                cross3(Vw, GVw, cw);
                cross3(Vv, GVv, cv);
                cross3(Vw, GVv, cx);
#pragma unroll
                for (int k = 0; k < 3; k++) { fw[k] += cw[k] + cv[k]; fv[k] += cx[k]; }
            }

            // bias accumulation: hh[a] += P_a · f_i  (a <= i)
#pragma unroll
            for (int a = 0; a < NJ; a++) {
                if (a <= i) {
                    hh[a] += Pw[a][0] * fw[0] + Pw[a][1] * fw[1] + Pw[a][2] * fw[2] +
                             Pv[a][0] * fv[0] + Pv[a][1] * fv[1] + Pv[a][2] * fv[2];
                }
            }
            // tip wrench enters at the last link's frame
            if (i == NJ - 1) {
#pragma unroll
                for (int a = 0; a < NJ; a++) {
                    hh[a] += Pw[a][0] * sc.ft6[0] + Pw[a][1] * sc.ft6[1] + Pw[a][2] * sc.ft6[2] +
                             Pv[a][0] * sc.ft6[3] + Pv[a][1] * sc.ft6[4] + Pv[a][2] * sc.ft6[5];
                }
            }

            // mass-matrix accumulation: Mm[a,b] += P_a · (G_i P_b), b <= a <= i
#pragma unroll
            for (int bb2 = 0; bb2 < NJ; bb2++) {
                if (bb2 <= i) {
                    float Tw[3], Tv[3];
#pragma unroll
                    for (int r = 0; r < 3; r++) {
                        Tw[r] = Gi[r * 6 + 0] * Pw[bb2][0] + Gi[r * 6 + 1] * Pw[bb2][1] + Gi[r * 6 + 2] * Pw[bb2][2] +
                                Gi[r * 6 + 3] * Pv[bb2][0] + Gi[r * 6 + 4] * Pv[bb2][1] + Gi[r * 6 + 5] * Pv[bb2][2];
                        Tv[r] = Gi[(r + 3) * 6 + 0] * Pw[bb2][0] + Gi[(r + 3) * 6 + 1] * Pw[bb2][1] + Gi[(r + 3) * 6 + 2] * Pw[bb2][2] +
                                Gi[(r + 3) * 6 + 3] * Pv[bb2][0] + Gi[(r + 3) * 6 + 4] * Pv[bb2][1] + Gi[(r + 3) * 6 + 5] * Pv[bb2][2];
                    }
#pragma unroll
                    for (int a = 0; a < NJ; a++) {
                        if (a >= bb2 && a <= i) {
                            Mm[TRI(a, bb2)] += Pw[a][0] * Tw[0] + Pw[a][1] * Tw[1] + Pw[a][2] * Tw[2] +
                                               Pv[a][0] * Tv[0] + Pv[a][1] * Tv[1] + Pv[a][2] * Tv[2];
                        }
                    }
                }
            }
        }

        // ===== Cholesky solve: M dd = tau - h =====
        {
            float rhs[NJ];
#pragma unroll
            for (int i = 0; i < NJ; i++) rhs[i] = STV(i) - hh[i];
#pragma unroll
            for (int k2 = 0; k2 < NJ; k2++) {
                float s = Mm[TRI(k2, k2)];
#pragma unroll
                for (int m2 = 0; m2 < NJ; m2++)
                    if (m2 < k2) { float l = Mm[TRI(k2, m2)]; s -= l * l; }
                float inv = rsqrtf(s);
                Mm[TRI(k2, k2)] = inv;
#pragma unroll
                for (int r = 0; r < NJ; r++) {
                    if (r > k2) {
                        float s2 = Mm[TRI(r, k2)];
#pragma unroll
                        for (int m2 = 0; m2 < NJ; m2++)
                            if (m2 < k2) s2 -= Mm[TRI(r, m2)] * Mm[TRI(k2, m2)];
                        Mm[TRI(r, k2)] = s2 * inv;
                    }
                }
            }
            float y[NJ];
#pragma unroll
            for (int i = 0; i < NJ; i++) {
                float s = rhs[i];
#pragma unroll
                for (int j = 0; j < NJ; j++)
                    if (j < i) s -= Mm[TRI(i, j)] * y[j];
                y[i] = s * Mm[TRI(i, i)];
            }
#pragma unroll
            for (int ii = 0; ii < NJ; ii++) {
                const int i = NJ - 1 - ii;
                float s = y[i];
#pragma unroll
                for (int j = 0; j < NJ; j++)
                    if (j > i) s -= Mm[TRI(j, i)] * dd[j];
                dd[i] = s * Mm[TRI(i, i)];
            }
        }

        // ===== RK4 combine =====
        float w8 = (st == 0 || st == 3) ? 1.f : 2.f;
#pragma unroll
        for (int i = 0; i < NJ; i++) {
            SAQ(i) += w8 * ds[i];
            SAD(i) += w8 * dd[i];
        }
        if (st < 3) {
            float hc = (st == 2) ? DT_C : 0.5f * DT_C;
#pragma unroll
            for (int i = 0; i < NJ; i++) {
                qs[i] = SQ0(i) + hc * ds[i];
                ds[i] = SDQ0(i) + hc * dd[i];
            }
        }
    }

    const float PI_F = 3.14159265358979323846f;
    const float TWO_PI = 6.28318530717958647692f;
    float qf2[NJ], dqf[NJ];
#pragma unroll
    for (int i = 0; i < NJ; i++) {
        float vq = SQ0(i) + (DT_C / 6.f) * SAQ(i);
        float x = vq + PI_F;
        float r = fmodf(x, TWO_PI);
        if (r < 0.f) r += TWO_PI;
        qf2[i] = r - PI_F;
        float vd = SDQ0(i) + (DT_C / 6.f) * SAD(i);
        dqf[i] = fminf(fmaxf(vd, -MAXV), MAXV);
    }

    // ===== forward kinematics (end-effector x,y) =====
    float Rk[9] = {1.f, 0.f, 0.f, 0.f, 1.f, 0.f, 0.f, 0.f, 1.f};
    float pk[3] = {0.f, 0.f, 0.f};
#pragma unroll
    for (int i = 0; i < NJ; i++) {
        float Rm2[9];
        mm33(Rk, sc.MR[i], Rm2);
        float pm2[3];
        mv33(Rk, sc.Mp[i], pm2);
#pragma unroll
        for (int k = 0; k < 3; k++) pm2[k] += pk[k];
        float qi = qf2[i];
        float w[3] = {sc.A[i][0] * qi, sc.A[i][1] * qi, sc.A[i][2] * qi};
        float v[3] = {sc.A[i][3] * qi, sc.A[i][4] * qi, sc.A[i][5] * qi};
        float th = sc.nAw[i] * fabsf(qi);
        float th2 = th * th;
        float a, bb, cc;
        abc_coeffs(th, a, bb, cc);
        float Re[9], Vmx[9];
        rodr(Re, a, bb, w, th2);
        rodr(Vmx, bb, cc, w, th2);
        float pe[3];
        mv33(Vmx, v, pe);
        float Rn[9];
        mm33(Rm2, Re, Rn);
        float pn[3];
        mv33(Rm2, pe, pn);
#pragma unroll
        for (int k = 0; k < 3; k++) pk[k] = pn[k] + pm2[k];
#pragma unroll
        for (int k = 0; k < 9; k++) Rk[k] = Rn[k];
    }
    float pf[3];
    mv33(Rk, sc.Mp[NJ], pf);
    float eex = pf[0] + pk[0];
    float eey = pf[1] + pk[1];

    // ===== outputs: [n,14] state then [n,2] ee, concatenated flat =====
#pragma unroll
    for (int i = 0; i < NJ; i++) {
        out[b * 14 + i] = qf2[i];
        out[b * 14 + 7 + i] = dqf[i];
    }
    out[(size_t)n * 14 + b * 2 + 0] = eex;
    out[(size_t)n * 14 + b * 2 + 1] = eey;
}

extern "C" void kernel_launch(void* const* d_in, const int* in_sizes, int n_in,
                              void* d_out, int out_size) {
    const float* state = (const float*)d_in[0];
    const float* torque = (const float*)d_in[1];
    const float* M = (const float*)d_in[2];
    const float* A = (const float*)d_in[3];
    const float* L = (const float*)d_in[4];
    const float* g = (const float*)d_in[5];
    const float* f = (const float*)d_in[6];
    int n = in_sizes[0] / 14;
    int grid = (n + NT - 1) / NT;
    arm_kernel<<<grid, NT>>>(state, torque, M, A, L, g, f, (float*)d_out, n);
}